// round 10
// baseline (speedup 1.0000x reference)
#include <cuda_runtime.h>

// ---------------------------------------------------------------------------
// Multislice gradient step, fully custom FFT implementation (sm_103a).
//
// Pipeline (single illumination):
//   T[zz]   = exp(i*kappa*O[zz])                      (precomputed, planar)
//   u       = planewave(na_illum)
//   forward: u = T[zz]*u ; u = prop(u, PK)  (15x)
//   u = T[15]*u
//   u_pup   = ifft2(fft2(u) * Kf * P)                 (focus+pupil fused)
//   resid   = u_pup * (1 - sqrt(meas)/|u_pup|)
//   u_bp    = ifft2(fft2(resid) * conj(Kf*P))
//   backward (zz=15..1):
//     g[zz] = u_bp*conj(u)*conj(T[zz])*(-i*kappa)
//     u_bp  = prop(u_bp*conj(T[zz]), conj(PK))
//     u     = prop(u, conj(PK)) / T[zz-1]
//   g[0]    = u_bp*conj(u)*conj(T[0])*(-i*kappa)
//   out     = x - alpha*g
//
// Each prop = rowDIF -> colDIF*kern*(1/N^2)*colDIT -> rowDIT, all in-place
// digit-reversed (radix-4) — no reordering, kernel evaluated analytically
// at digit-reversed frequencies.
// ---------------------------------------------------------------------------

#define NDIM 1024
#define NPIX (1024*1024)
#define NZS  16

#define PI_D 3.14159265358979323846

// -------------------- device scratch (allowed: __device__ globals) ---------
__device__ float2 g_T  [(size_t)NZS * NPIX];   // 128 MB transmittance planes
__device__ float2 g_G  [(size_t)NZS * NPIX];   // 128 MB gradient planes
__device__ float2 g_U  [NPIX];                 // forward field
__device__ float2 g_Ubp[NPIX];                 // backprop field
__device__ float2 g_S  [NPIX];                 // frequency-domain scratch

// -------------------- complex helpers --------------------------------------
__device__ __forceinline__ float2 cadd(float2 a, float2 b){ return make_float2(a.x+b.x, a.y+b.y); }
__device__ __forceinline__ float2 csub(float2 a, float2 b){ return make_float2(a.x-b.x, a.y-b.y); }
__device__ __forceinline__ float2 cmul(float2 a, float2 b){ return make_float2(a.x*b.x-a.y*b.y, a.x*b.y+a.y*b.x); }
// a * conj(b)
__device__ __forceinline__ float2 cmulc(float2 a, float2 b){ return make_float2(a.x*b.x+a.y*b.y, a.y*b.x-a.x*b.y); }

// reverse 5 base-4 digits of a 10-bit index
__device__ __forceinline__ int rev4(int v){
    return ((v & 3) << 8) | (((v >> 2) & 3) << 6) | (((v >> 4) & 3) << 4)
         | (((v >> 6) & 3) << 2) | ((v >> 8) & 3);
}
// fft-order index -> signed frequency integer
__device__ __forceinline__ int fidx(int k){ return (k < 512) ? k : k - 1024; }

// -------------------- radix-4 butterflies (in shared) -----------------------
// Forward DIF stage, span m (m = 256,64,16,4,1). 256 butterflies per 1024-FFT.
__device__ __forceinline__ void butterfly_fwd(float2* d, const float2* W, int t, int m){
    int j  = t & (m - 1);
    int i0 = ((t - j) << 2) + j;
    float2 a0 = d[i0], a1 = d[i0+m], a2 = d[i0+2*m], a3 = d[i0+3*m];
    float2 t0 = cadd(a0,a2), t1 = csub(a0,a2);
    float2 t2 = cadd(a1,a3), u  = csub(a1,a3);
    float2 mi = make_float2(u.y, -u.x);         // -i*u
    int e = j * (256 / m);
    float2 w1 = W[e], w2 = W[2*e], w3 = W[3*e];
    d[i0]       = cadd(t0,t2);
    d[i0+m]     = cmul(cadd(t1,mi), w1);
    d[i0+2*m]   = cmul(csub(t0,t2), w2);
    d[i0+3*m]   = cmul(csub(t1,mi), w3);
}
// Inverse DIT stage, span m (m = 1,4,16,64,256). Uses conj twiddles.
__device__ __forceinline__ void butterfly_inv(float2* d, const float2* W, int t, int m){
    int j  = t & (m - 1);
    int i0 = ((t - j) << 2) + j;
    int e = j * (256 / m);
    float2 w1 = W[e], w2 = W[2*e], w3 = W[3*e];
    float2 c0 = d[i0];
    float2 c1 = cmulc(d[i0+m],   w1);
    float2 c2 = cmulc(d[i0+2*m], w2);
    float2 c3 = cmulc(d[i0+3*m], w3);
    float2 t0 = cadd(c0,c2), t1 = csub(c0,c2);
    float2 t2 = cadd(c1,c3), u  = csub(c1,c3);
    float2 pi = make_float2(-u.y, u.x);         // +i*u
    d[i0]       = cadd(t0,t2);
    d[i0+m]     = cadd(t1,pi);
    d[i0+2*m]   = csub(t0,t2);
    d[i0+3*m]   = csub(t1,pi);
}

__device__ __forceinline__ void fill_twiddles(float2* W, int tid){
    #pragma unroll
    for (int i = 0; i < 4; i++){
        int k = tid + i*256;
        float s, c;
        sincospif(-(float)k * (1.0f/512.0f), &s, &c);   // exp(-2*pi*i*k/1024)
        W[k] = make_float2(c, s);
    }
}

// -------------------- row passes --------------------------------------------
// PRE: 0 = plain, 1 = multiply by T plane, 2 = planewave * T plane, 3 = mulT + store product
template<int PRE>
__global__ void __launch_bounds__(256) k_row_fwd(const float2* in, float2* out,
                                                 const float2* Tpl, float2* store,
                                                 const float* na)
{
    __shared__ float2 sd[1024];
    __shared__ float2 sw[1024];
    int tid = threadIdx.x;
    int r   = blockIdx.x;
    fill_twiddles(sw, tid);

    float t0 = 0.f, t1 = 0.f, yf = 0.f;
    if (PRE == 2){
        const float dfx = (float)(1.0/(0.325*1024.0));
        t0 = rintf((na[0]*2.0f)/dfx)*dfx;    // na/WL, WL=0.5
        t1 = rintf((na[1]*2.0f)/dfx)*dfx;
        yf = (float)((double)(r - 512) * 0.325);
    }
    size_t rowoff = (size_t)r * 1024;
    #pragma unroll
    for (int i = 0; i < 4; i++){
        int cidx = tid + i*256;
        size_t g = rowoff + cidx;
        float2 v;
        if (PRE == 2){
            float xf = (float)((double)(cidx - 512) * 0.325);
            float ph = (float)(2.0*PI_D) * (t0*xf + t1*yf);
            float s, c; sincosf(ph, &s, &c);
            v = cmul(make_float2(c, s), Tpl[g]);
        } else if (PRE == 1 || PRE == 3){
            v = cmul(in[g], Tpl[g]);
            if (PRE == 3) store[g] = v;
        } else {
            v = in[g];
        }
        sd[cidx] = v;
    }
    __syncthreads();
    #pragma unroll
    for (int m = 256; m >= 1; m >>= 2){ butterfly_fwd(sd, sw, tid, m); __syncthreads(); }
    #pragma unroll
    for (int i = 0; i < 4; i++){
        int cidx = tid + i*256;
        out[rowoff + cidx] = sd[cidx];
    }
}

// POST: 0 = plain, 1 = amplitude-replacement residual, 2 = divide by T plane
template<int POST>
__global__ void __launch_bounds__(256) k_row_inv(const float2* in, float2* out,
                                                 const float2* Tpl, const float* meas)
{
    __shared__ float2 sd[1024];
    __shared__ float2 sw[1024];
    int tid = threadIdx.x;
    int r   = blockIdx.x;
    fill_twiddles(sw, tid);
    size_t rowoff = (size_t)r * 1024;
    #pragma unroll
    for (int i = 0; i < 4; i++){
        int cidx = tid + i*256;
        sd[cidx] = in[rowoff + cidx];
    }
    __syncthreads();
    #pragma unroll
    for (int m = 1; m <= 256; m <<= 2){ butterfly_inv(sd, sw, tid, m); __syncthreads(); }
    #pragma unroll
    for (int i = 0; i < 4; i++){
        int cidx = tid + i*256;
        size_t g = rowoff + cidx;
        float2 v = sd[cidx];
        if (POST == 1){
            float a  = sqrtf(meas[g]);
            float mg = sqrtf(v.x*v.x + v.y*v.y);
            float f  = 1.0f - a/mg;
            v.x *= f; v.y *= f;
        } else if (POST == 2){
            float2 w = Tpl[g];
            float inv = 1.0f/(w.x*w.x + w.y*w.y);
            float2 q = cmulc(v, w);
            v = make_float2(q.x*inv, q.y*inv);
        }
        out[g] = v;
    }
}

// -------------------- fused column pass -------------------------------------
// In-place on d: colDIF -> multiply by analytic kernel (mask * exp(i*phc*kz) * scale)
// at digit-reversed frequencies -> colDIT.
// 8 columns per block; shared stride 1026 float2 per column (conflict-free).
#define COLSTRIDE 1026
#define COLSMEM   ((8*COLSTRIDE + 1024) * (int)sizeof(float2))

__global__ void __launch_bounds__(256) k_col(float2* d, float phc, float scale)
{
    extern __shared__ float2 sm[];
    float2* W = sm + 8*COLSTRIDE;
    int tid = threadIdx.x;
    int c0  = blockIdx.x * 8;
    fill_twiddles(W, tid);
    #pragma unroll
    for (int i = 0; i < 32; i++){
        int l = tid + i*256;
        int p = l >> 3, c = l & 7;
        sm[c*COLSTRIDE + p] = d[(size_t)p*1024 + c0 + c];
    }
    __syncthreads();
    #pragma unroll
    for (int m = 256; m >= 1; m >>= 2){
        #pragma unroll
        for (int c = 0; c < 8; c++) butterfly_fwd(sm + c*COLSTRIDE, W, tid, m);
        __syncthreads();
    }
    // pointwise kernel multiply at digit-reversed frequencies
    const double R2LIM = ((0.65/0.5)*(0.65/0.5)) * ((0.325*1024.0)*(0.325*1024.0));
    const float  DFX2  = (float)(1.0/((0.325*1024.0)*(0.325*1024.0)));
    int fx[8];
    #pragma unroll
    for (int c = 0; c < 8; c++) fx[c] = fidx(rev4(c0 + c));
    #pragma unroll
    for (int i = 0; i < 32; i++){
        int l = tid + i*256;
        int p = l >> 3, c = l & 7;
        int fy = fidx(rev4(p));
        int r2 = fx[c]*fx[c] + fy*fy;
        float2 v = sm[c*COLSTRIDE + p];
        float2 o;
        if ((double)r2 < R2LIM){
            float kz = sqrtf(4.0f - (float)r2 * DFX2);   // (1/WL)^2 = 4
            float s, cc; sincosf(phc * kz, &s, &cc);
            o = cmul(v, make_float2(cc*scale, s*scale));
        } else {
            o = make_float2(0.f, 0.f);
        }
        sm[c*COLSTRIDE + p] = o;
    }
    __syncthreads();
    #pragma unroll
    for (int m = 1; m <= 256; m <<= 2){
        #pragma unroll
        for (int c = 0; c < 8; c++) butterfly_inv(sm + c*COLSTRIDE, W, tid, m);
        __syncthreads();
    }
    #pragma unroll
    for (int i = 0; i < 32; i++){
        int l = tid + i*256;
        int p = l >> 3, c = l & 7;
        d[(size_t)p*1024 + c0 + c] = sm[c*COLSTRIDE + p];
    }
}

// -------------------- pointwise kernels -------------------------------------
__global__ void __launch_bounds__(256) k_T(const float* x, float2* T)
{
    int p = blockIdx.x*256 + threadIdx.x;
    const float KAP = (float)(2.0*PI_D*6.5);
    float buf[32];
    float4* b4 = (float4*)buf;
    const float4* xb = (const float4*)(x + (size_t)p*32);
    #pragma unroll
    for (int i = 0; i < 8; i++) b4[i] = xb[i];
    #pragma unroll
    for (int zz = 0; zz < 16; zz++){
        float e = expf(-KAP * buf[16 + zz]);       // exp(-kappa*Im(O))
        float s, c; sincosf(KAP * buf[zz], &s, &c);
        T[(size_t)zz*NPIX + p] = make_float2(e*c, e*s);
    }
}

// g = u_bp*conj(u)*conj(T)*(-i*kappa); optionally prep = u_bp*conj(T)
__global__ void __launch_bounds__(256) k_grad(const float2* ubp, const float2* u,
                                              const float2* T, float2* g,
                                              float2* prep, int doPrep)
{
    int p = blockIdx.x*256 + threadIdx.x;
    const float KAP = (float)(2.0*PI_D*6.5);
    float2 b = ubp[p], a = u[p], t = T[p];
    float2 m1 = cmulc(b, a);
    float2 m2 = cmulc(m1, t);
    g[p] = make_float2(KAP*m2.y, -KAP*m2.x);      // * (-i*kappa)
    if (doPrep) prep[p] = cmulc(b, t);
}

__global__ void __launch_bounds__(256) k_out(const float* x, const float2* G,
                                             const float* alpha, float* out)
{
    int p = blockIdx.x*256 + threadIdx.x;
    float al = alpha[0];
    float buf[32];
    float4* b4 = (float4*)buf;
    const float4* xb = (const float4*)(x + (size_t)p*32);
    #pragma unroll
    for (int i = 0; i < 8; i++) b4[i] = xb[i];
    #pragma unroll
    for (int zz = 0; zz < 16; zz++){
        float2 g = G[(size_t)zz*NPIX + p];
        buf[zz]      -= al * g.x;
        buf[16 + zz] -= al * g.y;
    }
    float4* ob = (float4*)(out + (size_t)p*32);
    #pragma unroll
    for (int i = 0; i < 8; i++) ob[i] = b4[i];
}

// -------------------- launch ------------------------------------------------
extern "C" void kernel_launch(void* const* d_in, const int* in_sizes, int n_in,
                              void* d_out, int out_size)
{
    (void)in_sizes; (void)n_in; (void)out_size;
    const float* x     = (const float*)d_in[0];
    const float* meas  = (const float*)d_in[1];
    const float* na    = (const float*)d_in[2];
    const float* alpha = (const float*)d_in[3];
    float* out = (float*)d_out;

    float2 *T, *G, *U, *Ubp, *S;
    cudaGetSymbolAddress((void**)&T,   g_T);
    cudaGetSymbolAddress((void**)&G,   g_G);
    cudaGetSymbolAddress((void**)&U,   g_U);
    cudaGetSymbolAddress((void**)&Ubp, g_Ubp);
    cudaGetSymbolAddress((void**)&S,   g_S);

    cudaFuncSetAttribute(k_col, cudaFuncAttributeMaxDynamicSharedMemorySize, COLSMEM);

    const float SCALE  = 1.0f / 1048576.0f;                 // ifft2 norm, folded
    const float PHC_PK = (float)(2.0*PI_D * 3.25);          // 2*pi*DZ
    const float PHC_F  = (float)(2.0*PI_D * (-24.375));     // 2*pi*(-DZ*(NZ-1)/2)

    dim3 gr(1024), gp(4096), gc(128);
    const int bt = 256;

    // transmittance planes
    k_T<<<gp, bt>>>(x, T);

    // forward multislice (15 propagations)
    for (int zz = 0; zz < 15; zz++){
        if (zz == 0) k_row_fwd<2><<<gr, bt>>>(nullptr, S, T, nullptr, na);
        else         k_row_fwd<1><<<gr, bt>>>(U, S, T + (size_t)zz*NPIX, nullptr, nullptr);
        k_col<<<gc, bt, COLSMEM>>>(S, PHC_PK, SCALE);
        k_row_inv<0><<<gr, bt>>>(S, U, nullptr, nullptr);
    }
    // slice 15 multiply (store product into U) + focus*pupil prop, residual fused
    k_row_fwd<3><<<gr, bt>>>(U, S, T + (size_t)15*NPIX, U, nullptr);
    k_col<<<gc, bt, COLSMEM>>>(S, PHC_F, SCALE);
    k_row_inv<1><<<gr, bt>>>(S, Ubp, nullptr, meas);
    // backprop residual through conj(pupil*focus)
    k_row_fwd<0><<<gr, bt>>>(Ubp, S, nullptr, nullptr, nullptr);
    k_col<<<gc, bt, COLSMEM>>>(S, -PHC_F, SCALE);
    k_row_inv<0><<<gr, bt>>>(S, Ubp, nullptr, nullptr);

    // backward slice loop
    for (int zz = 15; zz >= 1; zz--){
        k_grad<<<gp, bt>>>(Ubp, U, T + (size_t)zz*NPIX, G + (size_t)zz*NPIX, Ubp, 1);
        // u_bp = prop(u_bp*conj(T[zz]), conj(PK))
        k_row_fwd<0><<<gr, bt>>>(Ubp, S, nullptr, nullptr, nullptr);
        k_col<<<gc, bt, COLSMEM>>>(S, -PHC_PK, SCALE);
        k_row_inv<0><<<gr, bt>>>(S, Ubp, nullptr, nullptr);
        // u = prop(u, conj(PK)) / T[zz-1]
        k_row_fwd<0><<<gr, bt>>>(U, S, nullptr, nullptr, nullptr);
        k_col<<<gc, bt, COLSMEM>>>(S, -PHC_PK, SCALE);
        k_row_inv<2><<<gr, bt>>>(S, U, T + (size_t)(zz-1)*NPIX, nullptr);
    }
    k_grad<<<gp, bt>>>(Ubp, U, T, G, nullptr, 0);

    // out = x - alpha*g
    k_out<<<gp, bt>>>(x, G, alpha, out);
}

// round 12
// speedup vs baseline: 2.1158x; 2.1158x over previous
#include <cuda_runtime.h>

// ---------------------------------------------------------------------------
// Multislice gradient step — custom radix-4 FFT, bank-conflict-free shared
// access (XOR swizzle), register boundary stages, cross-prop kernel fusion.
// ---------------------------------------------------------------------------

#define NPIX (1024*1024)
#define NZS  16
#define PI_D 3.14159265358979323846
#define KAPF ((float)(2.0*PI_D*6.5))

// -------------------- device scratch ---------------------------------------
__device__ float2 g_T [(size_t)NZS*NPIX];   // transmittance planes
__device__ float2 g_G [(size_t)NZS*NPIX];   // gradient planes
__device__ float2 g_U [NPIX];               // spatial u field
__device__ float2 g_Sa[NPIX];               // freq scratch (fwd / ubp chain)
__device__ float2 g_Sb[NPIX];               // freq scratch (u chain)

// -------------------- complex helpers --------------------------------------
__device__ __forceinline__ float2 cadd(float2 a, float2 b){ return make_float2(a.x+b.x, a.y+b.y); }
__device__ __forceinline__ float2 csub(float2 a, float2 b){ return make_float2(a.x-b.x, a.y-b.y); }
__device__ __forceinline__ float2 cmul(float2 a, float2 b){ return make_float2(a.x*b.x-a.y*b.y, a.x*b.y+a.y*b.x); }
__device__ __forceinline__ float2 cmulc(float2 a, float2 b){ return make_float2(a.x*b.x+a.y*b.y, a.y*b.x-a.x*b.y); }

// bank swizzle: folds bits[4..] into low-4 bits; conflict-free for all
// stride patterns used (1,4,16,64 and grouped radix-4 patterns)
__device__ __forceinline__ int swz(int a){ return a ^ ((5*(a>>4)) & 15); }

__device__ __forceinline__ int rev4(int v){
    return ((v & 3) << 8) | (((v >> 2) & 3) << 6) | (((v >> 4) & 3) << 4)
         | (((v >> 6) & 3) << 2) | ((v >> 8) & 3);
}
__device__ __forceinline__ int fidx(int k){ return (k < 512) ? k : k - 1024; }

__device__ __forceinline__ void fill_tw(float2* W, int tid){
    #pragma unroll
    for (int i = 0; i < 4; i++){
        int k = tid + i*256;
        float s, c;
        sincospif(-(float)k * (1.0f/512.0f), &s, &c);   // exp(-2*pi*i*k/1024)
        W[swz(k)] = make_float2(c, s);
    }
}

// -------------------- shared-memory radix-4 stages --------------------------
__device__ __forceinline__ void st_fwd(float2* d, const float2* W, int t, int m){
    int j  = t & (m - 1);
    int i0 = ((t - j) << 2) + j;
    float2 a0 = d[swz(i0)], a1 = d[swz(i0+m)], a2 = d[swz(i0+2*m)], a3 = d[swz(i0+3*m)];
    float2 t0 = cadd(a0,a2), t1 = csub(a0,a2);
    float2 t2 = cadd(a1,a3), u  = csub(a1,a3);
    float2 mi = make_float2(u.y, -u.x);
    float2 w1 = W[swz(j * (256/m))];
    float2 w2 = cmul(w1,w1), w3 = cmul(w2,w1);
    d[swz(i0)]     = cadd(t0,t2);
    d[swz(i0+m)]   = cmul(cadd(t1,mi), w1);
    d[swz(i0+2*m)] = cmul(csub(t0,t2), w2);
    d[swz(i0+3*m)] = cmul(csub(t1,mi), w3);
}
__device__ __forceinline__ void st_inv(float2* d, const float2* W, int t, int m){
    int j  = t & (m - 1);
    int i0 = ((t - j) << 2) + j;
    float2 w1 = W[swz(j * (256/m))];
    float2 w2 = cmul(w1,w1), w3 = cmul(w2,w1);
    float2 c0 = d[swz(i0)];
    float2 c1 = cmulc(d[swz(i0+m)],   w1);
    float2 c2 = cmulc(d[swz(i0+2*m)], w2);
    float2 c3 = cmulc(d[swz(i0+3*m)], w3);
    float2 t0 = cadd(c0,c2), t1 = csub(c0,c2);
    float2 t2 = cadd(c1,c3), u  = csub(c1,c3);
    float2 pi = make_float2(-u.y, u.x);
    d[swz(i0)]     = cadd(t0,t2);
    d[swz(i0+m)]   = cadd(t1,pi);
    d[swz(i0+2*m)] = csub(t0,t2);
    d[swz(i0+3*m)] = csub(t1,pi);
}

// -------------------- register boundary stages ------------------------------
// fwd first stage (m=256): inputs v[i] at logical t+256i, write shared
__device__ __forceinline__ void st256_fwd_reg(float2* d, const float2* W, int t, const float2 v[4]){
    float2 t0 = cadd(v[0],v[2]), t1 = csub(v[0],v[2]);
    float2 t2 = cadd(v[1],v[3]), u  = csub(v[1],v[3]);
    float2 mi = make_float2(u.y, -u.x);
    float2 w1 = W[swz(t)];
    float2 w2 = cmul(w1,w1), w3 = cmul(w2,w1);
    d[swz(t)]     = cadd(t0,t2);
    d[swz(t+256)] = cmul(cadd(t1,mi), w1);
    d[swz(t+512)] = cmul(csub(t0,t2), w2);
    d[swz(t+768)] = cmul(csub(t1,mi), w3);
}
// fwd last stage (m=1): read shared 4t..4t+3, outputs r[k] at logical 4t+k
__device__ __forceinline__ void st1_fwd_reg(const float2* d, int t, float2 r[4]){
    int i0 = 4*t;
    float2 a0 = d[swz(i0)], a1 = d[swz(i0+1)], a2 = d[swz(i0+2)], a3 = d[swz(i0+3)];
    float2 t0 = cadd(a0,a2), t1 = csub(a0,a2);
    float2 t2 = cadd(a1,a3), u  = csub(a1,a3);
    float2 mi = make_float2(u.y, -u.x);
    r[0] = cadd(t0,t2); r[1] = cadd(t1,mi); r[2] = csub(t0,t2); r[3] = csub(t1,mi);
}
// inv first stage (m=1): inputs r[k] at logical 4t+k, write shared
__device__ __forceinline__ void st1_inv_reg(float2* d, int t, const float2 r[4]){
    float2 t0 = cadd(r[0],r[2]), t1 = csub(r[0],r[2]);
    float2 t2 = cadd(r[1],r[3]), u  = csub(r[1],r[3]);
    float2 pi = make_float2(-u.y, u.x);
    int i0 = 4*t;
    d[swz(i0)]   = cadd(t0,t2);
    d[swz(i0+1)] = cadd(t1,pi);
    d[swz(i0+2)] = csub(t0,t2);
    d[swz(i0+3)] = csub(t1,pi);
}
// inv last stage (m=256): read shared t+256i, outputs spatial v[i] at t+256i
__device__ __forceinline__ void st256_inv_reg(const float2* d, const float2* W, int t, float2 v[4]){
    float2 w1 = W[swz(t)];
    float2 w2 = cmul(w1,w1), w3 = cmul(w2,w1);
    float2 c0 = d[swz(t)];
    float2 c1 = cmulc(d[swz(t+256)], w1);
    float2 c2 = cmulc(d[swz(t+512)], w2);
    float2 c3 = cmulc(d[swz(t+768)], w3);
    float2 t0 = cadd(c0,c2), t1 = csub(c0,c2);
    float2 t2 = cadd(c1,c3), u  = csub(c1,c3);
    float2 pi = make_float2(-u.y, u.x);
    v[0] = cadd(t0,t2); v[1] = cadd(t1,pi); v[2] = csub(t0,t2); v[3] = csub(t1,pi);
}

// inverse-row chain: global -> spatial v[4] (cidx = t + 256i)
__device__ __forceinline__ void row_inverse(const float2* __restrict__ in, size_t rowoff,
                                            float2* sd, const float2* sw, int t, float2 v[4])
{
    float2 r[4];
    const float4* ing = (const float4*)(in + rowoff + 4*t);
    float4 p0 = ing[0], p1 = ing[1];
    r[0] = make_float2(p0.x,p0.y); r[1] = make_float2(p0.z,p0.w);
    r[2] = make_float2(p1.x,p1.y); r[3] = make_float2(p1.z,p1.w);
    st1_inv_reg(sd, t, r);
    __syncthreads();
    st_inv(sd, sw, t, 4);  __syncthreads();
    st_inv(sd, sw, t, 16); __syncthreads();
    st_inv(sd, sw, t, 64); __syncthreads();
    st256_inv_reg(sd, sw, t, v);
}
// forward-row chain: spatial v[4] (cidx = t + 256i) -> global
__device__ __forceinline__ void row_forward(float2* __restrict__ out, size_t rowoff,
                                            float2* sd, const float2* sw, int t, const float2 v[4])
{
    st256_fwd_reg(sd, sw, t, v);
    __syncthreads();
    st_fwd(sd, sw, t, 64); __syncthreads();
    st_fwd(sd, sw, t, 16); __syncthreads();
    st_fwd(sd, sw, t, 4);  __syncthreads();
    float2 r[4];
    st1_fwd_reg(sd, t, r);
    float4* og = (float4*)(out + rowoff + 4*t);
    og[0] = make_float4(r[0].x,r[0].y,r[1].x,r[1].y);
    og[1] = make_float4(r[2].x,r[2].y,r[3].x,r[3].y);
}

// -------------------- fused row kernels -------------------------------------
#define MID_MULT       1   // v *= T
#define MID_MULT_STORE 2   // v *= T; U = v
#define MID_RESID      3   // amplitude replacement residual
#define MID_GRAD       4   // G = v*conj(U)*conj(T)*(-i*kappa); v *= conj(T)
#define MID_DIV_STORE  5   // v /= T; U = v

template<int MID>
__global__ void __launch_bounds__(256) k_rowfused(const float2* __restrict__ in,
        float2* __restrict__ out, const float2* __restrict__ Tpl,
        const float2* __restrict__ Uin, float2* __restrict__ aux,
        const float* __restrict__ meas)
{
    __shared__ float2 sd[1024];
    __shared__ float2 sw[1024];
    int t = threadIdx.x;
    size_t rowoff = (size_t)blockIdx.x * 1024;
    fill_tw(sw, t);
    float2 v[4];
    row_inverse(in, rowoff, sd, sw, t, v);
    #pragma unroll
    for (int i = 0; i < 4; i++){
        size_t g = rowoff + t + 256*i;
        if (MID == MID_MULT){
            v[i] = cmul(v[i], Tpl[g]);
        } else if (MID == MID_MULT_STORE){
            v[i] = cmul(v[i], Tpl[g]);
            aux[g] = v[i];
        } else if (MID == MID_RESID){
            float a  = sqrtf(meas[g]);
            float mg = sqrtf(v[i].x*v[i].x + v[i].y*v[i].y);
            float f  = 1.0f - a/mg;
            v[i].x *= f; v[i].y *= f;
        } else if (MID == MID_GRAD){
            float2 tv = Tpl[g];
            float2 uu = Uin[g];
            float2 m1 = cmulc(v[i], uu);
            float2 m2 = cmulc(m1, tv);
            aux[g] = make_float2(KAPF*m2.y, -KAPF*m2.x);
            v[i] = cmulc(v[i], tv);
        } else if (MID == MID_DIV_STORE){
            float2 tv = Tpl[g];
            float inv = 1.0f/(tv.x*tv.x + tv.y*tv.y);
            float2 q  = cmulc(v[i], tv);
            v[i] = make_float2(q.x*inv, q.y*inv);
            aux[g] = v[i];
        }
    }
    __syncthreads();
    row_forward(out, rowoff, sd, sw, t, v);
}

// standalone forward: PRE 0 = plain, 2 = planewave * T
template<int PRE>
__global__ void __launch_bounds__(256) k_rowfwd(const float2* __restrict__ in,
        float2* __restrict__ out, const float2* __restrict__ Tpl,
        const float* __restrict__ na)
{
    __shared__ float2 sd[1024];
    __shared__ float2 sw[1024];
    int t = threadIdx.x;
    int r = blockIdx.x;
    size_t rowoff = (size_t)r * 1024;
    fill_tw(sw, t);
    float t0 = 0.f, t1 = 0.f, yf = 0.f;
    if (PRE == 2){
        const float dfx = (float)(1.0/(0.325*1024.0));
        t0 = rintf((na[0]*2.0f)/dfx)*dfx;
        t1 = rintf((na[1]*2.0f)/dfx)*dfx;
        yf = (float)((double)(r - 512) * 0.325);
    }
    float2 v[4];
    #pragma unroll
    for (int i = 0; i < 4; i++){
        int cidx = t + 256*i;
        size_t g = rowoff + cidx;
        if (PRE == 2){
            float xf = (float)((double)(cidx - 512) * 0.325);
            float ph = (float)(2.0*PI_D) * (t0*xf + t1*yf);
            float s, c; sincosf(ph, &s, &c);
            v[i] = cmul(make_float2(c, s), Tpl[g]);
        } else {
            v[i] = in[g];
        }
    }
    __syncthreads();          // twiddle table complete
    row_forward(out, rowoff, sd, sw, t, v);
}

// standalone inverse: divide by T, store spatial to Uout
__global__ void __launch_bounds__(256) k_rowinv_div(const float2* __restrict__ in,
        const float2* __restrict__ Tpl, float2* __restrict__ Uout)
{
    __shared__ float2 sd[1024];
    __shared__ float2 sw[1024];
    int t = threadIdx.x;
    size_t rowoff = (size_t)blockIdx.x * 1024;
    fill_tw(sw, t);
    float2 v[4];
    row_inverse(in, rowoff, sd, sw, t, v);
    #pragma unroll
    for (int i = 0; i < 4; i++){
        size_t g = rowoff + t + 256*i;
        float2 tv = Tpl[g];
        float inv = 1.0f/(tv.x*tv.x + tv.y*tv.y);
        float2 q  = cmulc(v[i], tv);
        Uout[g] = make_float2(q.x*inv, q.y*inv);
    }
}

// standalone inverse: final gradient g[0]
__global__ void __launch_bounds__(256) k_rowinv_grad(const float2* __restrict__ in,
        const float2* __restrict__ Uin, const float2* __restrict__ Tpl,
        float2* __restrict__ Gout)
{
    __shared__ float2 sd[1024];
    __shared__ float2 sw[1024];
    int t = threadIdx.x;
    size_t rowoff = (size_t)blockIdx.x * 1024;
    fill_tw(sw, t);
    float2 v[4];
    row_inverse(in, rowoff, sd, sw, t, v);
    #pragma unroll
    for (int i = 0; i < 4; i++){
        size_t g = rowoff + t + 256*i;
        float2 tv = Tpl[g];
        float2 uu = Uin[g];
        float2 m1 = cmulc(v[i], uu);
        float2 m2 = cmulc(m1, tv);
        Gout[g] = make_float2(KAPF*m2.y, -KAPF*m2.x);
    }
}

// -------------------- fused column pass -------------------------------------
// colDIF -> analytic kernel multiply (at digit-reversed freqs) -> colDIT,
// in-place. 8 columns per block, 512 threads (2 concurrent columns).
#define COLSTRIDE 1026
#define COLSMEM   ((8*COLSTRIDE + 1024) * (int)sizeof(float2))

__global__ void __launch_bounds__(512) k_col(float2* d, float phc, float scale)
{
    extern __shared__ float2 sm[];
    float2* W = sm + 8*COLSTRIDE;
    int t  = threadIdx.x;
    int tt = t & 255;
    int ch = t >> 8;             // 0 or 1: which column of the pair
    int c0 = blockIdx.x * 8;
    if (t < 256) fill_tw(W, t);
    #pragma unroll
    for (int i = 0; i < 16; i++){
        int l = t + i*512;
        int p = l >> 3, c = l & 7;
        sm[c*COLSTRIDE + swz(p)] = d[(size_t)p*1024 + c0 + c];
    }
    __syncthreads();
    #pragma unroll
    for (int m = 256; m >= 4; m >>= 2){
        #pragma unroll
        for (int cc = 0; cc < 4; cc++) st_fwd(sm + (ch + 2*cc)*COLSTRIDE, W, tt, m);
        __syncthreads();
    }
    // fused m=1 fwd + kernel multiply + m=1 inv (registers)
    const double R2LIM = ((0.65/0.5)*(0.65/0.5)) * ((0.325*1024.0)*(0.325*1024.0));
    const float  DFX2  = (float)(1.0/((0.325*1024.0)*(0.325*1024.0)));
    int fy[4];
    #pragma unroll
    for (int k = 0; k < 4; k++) fy[k] = fidx(rev4(4*tt + k));
    #pragma unroll
    for (int cc = 0; cc < 4; cc++){
        int c = ch + 2*cc;
        float2* dc = sm + c*COLSTRIDE;
        float2 rr[4];
        st1_fwd_reg(dc, tt, rr);
        int fxv = fidx(rev4(c0 + c));
        int fx2 = fxv*fxv;
        #pragma unroll
        for (int k = 0; k < 4; k++){
            int r2 = fx2 + fy[k]*fy[k];
            if ((double)r2 < R2LIM){
                float kz = sqrtf(4.0f - (float)r2 * DFX2);
                float s, cx; sincosf(phc * kz, &s, &cx);
                rr[k] = cmul(rr[k], make_float2(cx*scale, s*scale));
            } else {
                rr[k] = make_float2(0.f, 0.f);
            }
        }
        st1_inv_reg(dc, tt, rr);
    }
    __syncthreads();
    #pragma unroll
    for (int m = 4; m <= 256; m <<= 2){
        #pragma unroll
        for (int cc = 0; cc < 4; cc++) st_inv(sm + (ch + 2*cc)*COLSTRIDE, W, tt, m);
        __syncthreads();
    }
    #pragma unroll
    for (int i = 0; i < 16; i++){
        int l = t + i*512;
        int p = l >> 3, c = l & 7;
        d[(size_t)p*1024 + c0 + c] = sm[c*COLSTRIDE + swz(p)];
    }
}

// -------------------- pointwise kernels -------------------------------------
__global__ void __launch_bounds__(256) k_T(const float* __restrict__ x, float2* __restrict__ T)
{
    int p = blockIdx.x*256 + threadIdx.x;
    float buf[32];
    float4* b4 = (float4*)buf;
    const float4* xb = (const float4*)(x + (size_t)p*32);
    #pragma unroll
    for (int i = 0; i < 8; i++) b4[i] = xb[i];
    #pragma unroll
    for (int zz = 0; zz < 16; zz++){
        float e = expf(-KAPF * buf[16 + zz]);
        float s, c; sincosf(KAPF * buf[zz], &s, &c);
        T[(size_t)zz*NPIX + p] = make_float2(e*c, e*s);
    }
}

__global__ void __launch_bounds__(256) k_out(const float* __restrict__ x,
        const float2* __restrict__ G, const float* __restrict__ alpha,
        float* __restrict__ out)
{
    int p = blockIdx.x*256 + threadIdx.x;
    float al = alpha[0];
    float buf[32];
    float4* b4 = (float4*)buf;
    const float4* xb = (const float4*)(x + (size_t)p*32);
    #pragma unroll
    for (int i = 0; i < 8; i++) b4[i] = xb[i];
    #pragma unroll
    for (int zz = 0; zz < 16; zz++){
        float2 g = G[(size_t)zz*NPIX + p];
        buf[zz]      -= al * g.x;
        buf[16 + zz] -= al * g.y;
    }
    float4* ob = (float4*)(out + (size_t)p*32);
    #pragma unroll
    for (int i = 0; i < 8; i++) ob[i] = b4[i];
}

// -------------------- launch ------------------------------------------------
extern "C" void kernel_launch(void* const* d_in, const int* in_sizes, int n_in,
                              void* d_out, int out_size)
{
    (void)in_sizes; (void)n_in; (void)out_size;
    const float* x     = (const float*)d_in[0];
    const float* meas  = (const float*)d_in[1];
    const float* na    = (const float*)d_in[2];
    const float* alpha = (const float*)d_in[3];
    float* out = (float*)d_out;

    float2 *T, *G, *U, *Sa, *Sb;
    cudaGetSymbolAddress((void**)&T,  g_T);
    cudaGetSymbolAddress((void**)&G,  g_G);
    cudaGetSymbolAddress((void**)&U,  g_U);
    cudaGetSymbolAddress((void**)&Sa, g_Sa);
    cudaGetSymbolAddress((void**)&Sb, g_Sb);

    cudaFuncSetAttribute(k_col, cudaFuncAttributeMaxDynamicSharedMemorySize, COLSMEM);

    const float SCALE  = 1.0f / 1048576.0f;            // ifft2 norm
    const float PHC_PK = (float)(2.0*PI_D * 3.25);     // 2*pi*DZ
    const float PHC_F  = (float)(2.0*PI_D * (-24.375));// 2*pi*(-DZ*(NZ-1)/2)

    dim3 gr(1024), gp(4096), gc(128);
    const int bt = 256;

    k_T<<<gp, bt>>>(x, T);

    // ---- forward multislice: slice 0 start, then fused inv->xT->fwd chain
    k_rowfwd<2><<<gr, bt>>>(nullptr, Sa, T, na);
    k_col<<<gc, 512, COLSMEM>>>(Sa, PHC_PK, SCALE);
    for (int zz = 1; zz <= 14; zz++){
        k_rowfused<MID_MULT><<<gr, bt>>>(Sa, Sa, T + (size_t)zz*NPIX, nullptr, nullptr, nullptr);
        k_col<<<gc, 512, COLSMEM>>>(Sa, PHC_PK, SCALE);
    }
    // slice 15 multiply (store u to U), focus+pupil prop
    k_rowfused<MID_MULT_STORE><<<gr, bt>>>(Sa, Sa, T + (size_t)15*NPIX, nullptr, U, nullptr);
    k_col<<<gc, 512, COLSMEM>>>(Sa, PHC_F, SCALE);
    // residual + start of backprop through conj(pupil*focus)
    k_rowfused<MID_RESID><<<gr, bt>>>(Sa, Sa, nullptr, nullptr, nullptr, meas);
    k_col<<<gc, 512, COLSMEM>>>(Sa, -PHC_F, SCALE);

    // ---- start u backward chain: fwd(U) and prop by conj(PK)
    k_rowfwd<0><<<gr, bt>>>(U, Sb, nullptr, nullptr);
    k_col<<<gc, 512, COLSMEM>>>(Sb, -PHC_PK, SCALE);

    // ---- backward slice loop (fused): zz = 15..2
    for (int zz = 15; zz >= 2; zz--){
        // M_ubp: inv -> write g[zz] (uses U = u@zz, T[zz]) -> x conj(T[zz]) -> fwd
        k_rowfused<MID_GRAD><<<gr, bt>>>(Sa, Sa, T + (size_t)zz*NPIX, U, G + (size_t)zz*NPIX, nullptr);
        k_col<<<gc, 512, COLSMEM>>>(Sa, -PHC_PK, SCALE);
        // M_u: inv -> / T[zz-1] -> store U = u@(zz-1) -> fwd
        k_rowfused<MID_DIV_STORE><<<gr, bt>>>(Sb, Sb, T + (size_t)(zz-1)*NPIX, nullptr, U, nullptr);
        k_col<<<gc, 512, COLSMEM>>>(Sb, -PHC_PK, SCALE);
    }
    // zz = 1: grad + last ubp prop
    k_rowfused<MID_GRAD><<<gr, bt>>>(Sa, Sa, T + (size_t)1*NPIX, U, G + (size_t)1*NPIX, nullptr);
    k_col<<<gc, 512, COLSMEM>>>(Sa, -PHC_PK, SCALE);
    // u@0 (divide by T[0]), then final gradient g[0]
    k_rowinv_div <<<gr, bt>>>(Sb, T, U);
    k_rowinv_grad<<<gr, bt>>>(Sa, U, T, G);

    k_out<<<gp, bt>>>(x, G, alpha, out);
}